// round 12
// baseline (speedup 1.0000x reference)
#include <cuda_runtime.h>
#include <cuda_bf16.h>
#include <math.h>

#define CLOUDS 64
#define PPC    128
#define DIM    128
#define NNODES (CLOUDS * PPC)
#define EPSV   1e-5f

typedef unsigned long long ull;

// ---------------- scratch ------------------------------------------------------
__device__ float g_ps[128 * 128];
__device__ float g_pss[128 * 128];
__device__ float g_bstats[256];         // [0:128) scale, [128:256) shift
__device__ unsigned g_cnt;              // arrival ticket
__device__ unsigned g_cnt2;             // exit ticket (for reset)
__device__ unsigned g_flag;             // bstats-ready flag

// ---------------- helpers ------------------------------------------------------
__device__ __forceinline__ ull pack2(float lo, float hi) {
    ull r; asm("mov.b64 %0, {%1, %2};" : "=l"(r) : "f"(lo), "f"(hi)); return r;
}
__device__ __forceinline__ void unpack2(ull v, float& lo, float& hi) {
    asm("mov.b64 {%0, %1}, %2;" : "=f"(lo), "=f"(hi) : "l"(v));
}
__device__ __forceinline__ ull fma2(ull a, ull b, ull c) {
    ull d; asm("fma.rn.f32x2 %0, %1, %2, %3;" : "=l"(d) : "l"(a), "l"(b), "l"(c)); return d;
}
__device__ __forceinline__ ull add2(ull a, ull b) {
    ull d; asm("add.rn.f32x2 %0, %1, %2;" : "=l"(d) : "l"(a), "l"(b)); return d;
}
__device__ __forceinline__ float rsqrt_ap(float x) {
    float r; asm("rsqrt.approx.f32 %0, %1;" : "=f"(r) : "f"(x)); return r;
}
__device__ __forceinline__ float ex2_ap(float x) {
    float r; asm("ex2.approx.f32 %0, %1;" : "=f"(r) : "f"(x)); return r;
}

#define NEG1_2 0xBF800000BF800000ULL
#define LOG2E  1.4426950408889634f

// smem layout (float offsets):
//   ys    @ 0      16384 f  (64KB)  Y of full cloud  (ull view: [128 row][64 cp])
//   bufA  @ 16384  16384 f  (64KB)  xd (ull[64k][128r]) -> wsd (ull[128j][64i]) -> BN stage
//   bufB  @ 32768  16384 f  (64KB)  wp W1 (ull[128k][64cp]) -> zs (float[128][128]) -> reduce stage
//   xyzs  @ 49152  512 f
//   wxs   @ 49664  384 f
#define SM_FLOATS 50048

__global__ void __launch_bounds__(1024, 1)
mega(const float* __restrict__ X, const float* __restrict__ XYZ,
     const float* __restrict__ Wxyz, const float* __restrict__ bn_g,
     const float* __restrict__ bn_b, const float* __restrict__ W1,
     const float* __restrict__ b1, const float* __restrict__ ln_g,
     const float* __restrict__ ln_b, float* __restrict__ out) {
    extern __shared__ float sm[];
    float* ys   = sm;
    ull*   ysu  = (ull*)ys;
    float* bufA = sm + 16384;
    ull*   xd   = (ull*)bufA;       // GEMM X staging
    ull*   wsd  = (ull*)bufA;       // later: duplicated edge weights
    float* bufB = sm + 32768;
    ull*   wp   = (ull*)bufB;       // W1
    float* zs   = bufB;             // later: z matrix
    ull*   zsu  = (ull*)bufB;
    float* xyzs = sm + 49152;
    float* wxs  = sm + 49664;

    const int tid  = threadIdx.x;
    const int w    = tid >> 5;
    const int lane = tid & 31;

    const int cta   = blockIdx.x;
    const int node0 = (cta >> 1) << 7;
    const int i0    = (cta & 1) << 6;

    // ---------------- stage W1 (full, 64KB) + xyz + wxs -------------------------
    {
        const float4* W4 = (const float4*)W1;
        float4* d = (float4*)bufB;
        #pragma unroll
        for (int t = 0; t < 4; t++) d[tid + t * 1024] = W4[tid + t * 1024];
    }
    if (tid < 128) {
        const float* p = XYZ + (node0 + tid) * 3;
        xyzs[tid * 4 + 0] = p[0];
        xyzs[tid * 4 + 1] = p[1];
        xyzs[tid * 4 + 2] = p[2];
        xyzs[tid * 4 + 3] = 0.f;
    } else if (tid >= 512 && tid < 896) {
        wxs[tid - 512] = Wxyz[tid - 512];
    }

    // ---------------- GEMM: Y = X @ W1, two k-phases over shared xd buffer ------
    const int rowg = tid >> 6;   // 0..15 (8 rows each); warp-uniform
    const int cp   = tid & 63;   // 0..63 col-pairs

    ull acc[8];
    #pragma unroll
    for (int r = 0; r < 8; r++) acc[r] = 0ULL;

    #pragma unroll
    for (int ph = 0; ph < 2; ph++) {
        const int kb = ph * 64;
        // stage xd[k][r] = (x,x) for k in [kb, kb+64)
        {
            int r  = tid >> 3;          // 0..127
            int fq = tid & 7;           // 0..7
            const float4* X4 = (const float4*)X + (ull)(node0 + r) * 32 + (kb >> 2);
            #pragma unroll
            for (int h = 0; h < 2; h++) {
                int q = fq + h * 8;     // 0..15
                float4 v = X4[q];
                xd[(q * 4 + 0) * 128 + r] = pack2(v.x, v.x);
                xd[(q * 4 + 1) * 128 + r] = pack2(v.y, v.y);
                xd[(q * 4 + 2) * 128 + r] = pack2(v.z, v.z);
                xd[(q * 4 + 3) * 128 + r] = pack2(v.w, v.w);
            }
        }
        __syncthreads();
        #pragma unroll 4
        for (int k = 0; k < 64; k++) {
            const ulonglong2* xv = (const ulonglong2*)(xd + k * 128 + rowg * 8);
            ulonglong2 x0 = xv[0], x1 = xv[1], x2 = xv[2], x3 = xv[3];
            ull xr[8] = {x0.x, x0.y, x1.x, x1.y, x2.x, x2.y, x3.x, x3.y};
            ull wv = wp[(kb + k) * 64 + cp];
            #pragma unroll
            for (int r = 0; r < 8; r++) acc[r] = fma2(xr[r], wv, acc[r]);
        }
        __syncthreads();   // done reading xd this phase (before restage / reuse)
    }
    // write Y to ys
    #pragma unroll
    for (int r = 0; r < 8; r++) ysu[(rowg * 8 + r) * 64 + cp] = acc[r];
    __syncthreads();       // ys ready; bufA & bufB free

    // ---------------- zs (bufB) and wsd (bufA) ----------------------------------
    #pragma unroll
    for (int t = 0; t < 16; t++) {
        int idx = tid + t * 1024;
        int jn = idx >> 7;
        int d  = idx & 127;
        zs[idx] = xyzs[(jn << 2) + 0] * wxs[d]
                + xyzs[(jn << 2) + 1] * wxs[128 + d]
                + xyzs[(jn << 2) + 2] * wxs[256 + d];
    }
    #pragma unroll
    for (int t = 0; t < 8; t++) {
        int idx = tid + t * 1024;     // 0..8191
        int ii = idx & 63;            // local i
        int jj = idx >> 6;            // j 0..127
        float dx = xyzs[((i0 + ii) << 2) + 0] - xyzs[(jj << 2) + 0];
        float dy = xyzs[((i0 + ii) << 2) + 1] - xyzs[(jj << 2) + 1];
        float dz = xyzs[((i0 + ii) << 2) + 2] - xyzs[(jj << 2) + 2];
        float d2 = dx * dx + dy * dy + dz * dz;
        float dist = d2 * rsqrt_ap(fmaxf(d2, 1e-30f));
        float wv = ex2_ap(-dist * LOG2E);
        wsd[(jj << 6) + ii] = pack2(wv, wv);
    }

    // ---------------- per-thread setup ------------------------------------------
    const int iA = w << 1;            // local i (even)
    const int iB = iA + 1;
    const int dbase = lane << 2;      // 4 d per thread

    ull b1p[2];
    {
        const ull* b1u = (const ull*)b1;
        b1p[0] = b1u[lane * 2 + 0];
        b1p[1] = b1u[lane * 2 + 1];
    }
    __syncthreads();     // zs + wsd ready

    ull yiA[2], yiB[2], ziA[2], ziB[2];
    {
        int offA = (i0 + iA) * 64 + lane * 2;
        int offB = (i0 + iB) * 64 + lane * 2;
        yiA[0] = ysu[offA]; yiA[1] = ysu[offA + 1];
        yiB[0] = ysu[offB]; yiB[1] = ysu[offB + 1];
        ziA[0] = zsu[offA]; ziA[1] = zsu[offA + 1];
        ziB[0] = zsu[offB]; ziB[1] = zsu[offB + 1];
    }
    ull a1A[2] = {0ULL, 0ULL}, a1B[2] = {0ULL, 0ULL};
    ull a2A[2] = {0ULL, 0ULL}, a2B[2] = {0ULL, 0ULL};

    // ---------------- fused main loop over j ------------------------------------
    #pragma unroll 4
    for (int j = 0; j < 128; j++) {
        ulonglong2 wv2 = *(const ulonglong2*)(wsd + (j << 6) + iA); // (wA,wA),(wB,wB)
        ulonglong2 yj  = *(const ulonglong2*)(ysu + (j << 6) + lane * 2);
        ulonglong2 zj  = *(const ulonglong2*)(zsu + (j << 6) + lane * 2);
        ull yjp[2] = {yj.x, yj.y};
        ull zjp[2] = {zj.x, zj.y};
        #pragma unroll
        for (int p = 0; p < 2; p++) {
            float lo, hi;
            // branch-1, node iA
            ull df = fma2(yjp[p], NEG1_2, yiA[p]);
            ull t  = fma2(wv2.x, df, b1p[p]);
            unpack2(t, lo, hi);
            lo = fmaxf(lo, 0.f); hi = fmaxf(hi, 0.f);
            a1A[p] = add2(a1A[p], pack2(lo, hi));
            // branch-1, node iB
            df = fma2(yjp[p], NEG1_2, yiB[p]);
            t  = fma2(wv2.y, df, b1p[p]);
            unpack2(t, lo, hi);
            lo = fmaxf(lo, 0.f); hi = fmaxf(hi, 0.f);
            a1B[p] = add2(a1B[p], pack2(lo, hi));
            // branch-2, node iA
            ull dz = fma2(zjp[p], NEG1_2, ziA[p]);
            unpack2(dz, lo, hi);
            lo = fmaxf(lo, 0.f); hi = fmaxf(hi, 0.f);
            a2A[p] = add2(a2A[p], pack2(lo, hi));
            // branch-2, node iB
            dz = fma2(zjp[p], NEG1_2, ziB[p]);
            unpack2(dz, lo, hi);
            lo = fmaxf(lo, 0.f); hi = fmaxf(hi, 0.f);
            a2B[p] = add2(a2B[p], pack2(lo, hi));
        }
    }

    // ---------------- epilogue: LN (warp shuffles) -------------------------------
    float afA[4], afB[4], pA[4], pB[4];
    #pragma unroll
    for (int p = 0; p < 2; p++) {
        float bl, bh; unpack2(b1p[p], bl, bh);
        float rb0 = fmaxf(bl, 0.f), rb1 = fmaxf(bh, 0.f);
        float lo, hi;
        unpack2(a1A[p], lo, hi);
        afA[2 * p + 0] = lo - rb0;  afA[2 * p + 1] = hi - rb1;   // remove self edge
        unpack2(a1B[p], lo, hi);
        afB[2 * p + 0] = lo - rb0;  afB[2 * p + 1] = hi - rb1;
        unpack2(a2A[p], lo, hi);
        pA[2 * p + 0] = lo;  pA[2 * p + 1] = hi;                  // p2 (self edge = 0)
        unpack2(a2B[p], lo, hi);
        pB[2 * p + 0] = lo;  pB[2 * p + 1] = hi;
    }
    float sA = 0.f, qA = 0.f, sB = 0.f, qB = 0.f;
    #pragma unroll
    for (int k = 0; k < 4; k++) {
        sA += afA[k]; qA += afA[k] * afA[k];
        sB += afB[k]; qB += afB[k] * afB[k];
    }
    #pragma unroll
    for (int off = 16; off > 0; off >>= 1) {
        sA += __shfl_xor_sync(0xffffffffu, sA, off);
        qA += __shfl_xor_sync(0xffffffffu, qA, off);
        sB += __shfl_xor_sync(0xffffffffu, sB, off);
        qB += __shfl_xor_sync(0xffffffffu, qB, off);
    }
    float muA  = sA * (1.f / 128.f);
    float invA = 1.f / sqrtf(qA * (1.f / 128.f) - muA * muA + EPSV);
    float muB  = sB * (1.f / 128.f);
    float invB = 1.f / sqrtf(qB * (1.f / 128.f) - muB * muB + EPSV);

    // ---------------- BN partials -> global --------------------------------------
    __syncthreads();   // everyone done reading wsd/zs before bufA reuse
    {
        float4 s4, q4;
        s4.x = pA[0] + pB[0]; s4.y = pA[1] + pB[1];
        s4.z = pA[2] + pB[2]; s4.w = pA[3] + pB[3];
        q4.x = pA[0] * pA[0] + pB[0] * pB[0];
        q4.y = pA[1] * pA[1] + pB[1] * pB[1];
        q4.z = pA[2] * pA[2] + pB[2] * pB[2];
        q4.w = pA[3] * pA[3] + pB[3] * pB[3];
        *(float4*)(bufA + w * 128 + dbase)        = s4;
        *(float4*)(bufA + 4096 + w * 128 + dbase) = q4;
    }
    __syncthreads();
    if (tid < 128) {
        float S = 0.f, SS = 0.f;
        #pragma unroll 8
        for (int ww = 0; ww < 32; ww++) {
            S  += bufA[ww * 128 + tid];
            SS += bufA[4096 + ww * 128 + tid];
        }
        g_ps[cta * 128 + tid]  = S;
        g_pss[cta * 128 + tid] = SS;
    }

    // ---------------- grid sync: last CTA computes bstats ------------------------
    __shared__ unsigned s_tk;
    __threadfence();
    if (tid == 0) s_tk = atomicAdd(&g_cnt, 1u);
    __syncthreads();
    if (s_tk == 127u) {
        __threadfence();
        const int d   = tid & 127;
        const int grp = tid >> 7;   // 0..7, 16 CTAs each
        const float* ps  = g_ps  + grp * 16 * 128 + d;
        const float* pss = g_pss + grp * 16 * 128 + d;
        float S = 0.f, SS = 0.f;
        #pragma unroll 8
        for (int c = 0; c < 16; c++) {
            S  += ps[c * 128];
            SS += pss[c * 128];
        }
        bufB[grp * 128 + d]        = S;
        bufB[1024 + grp * 128 + d] = SS;
        __syncthreads();
        if (tid < 128) {
            float St = 0.f, SSt = 0.f;
            #pragma unroll
            for (int g = 0; g < 8; g++) {
                St  += bufB[g * 128 + tid];
                SSt += bufB[1024 + g * 128 + tid];
            }
            float mu  = St * (1.f / (float)NNODES);
            float var = SSt * (1.f / (float)NNODES) - mu * mu;
            float inv = 1.f / sqrtf(var + EPSV);
            float scale = inv * bn_g[tid];
            g_bstats[tid]       = scale;
            g_bstats[128 + tid] = bn_b[tid] - mu * scale;
        }
        __syncthreads();
        if (tid == 0) {
            __threadfence();
            atomicExch(&g_flag, 1u);
        }
    } else if (tid == 0) {
        while (atomicAdd(&g_flag, 0u) == 0u) __nanosleep(64);
    }
    __syncthreads();
    __threadfence();

    // ---------------- final write: out = x + LN(p1) + BN(p2) ---------------------
    float4 gv = *(const float4*)(ln_g + dbase);
    float4 bv = *(const float4*)(ln_b + dbase);
    float4 sc = *(const float4*)(g_bstats + dbase);
    float4 sh = *(const float4*)(g_bstats + 128 + dbase);

    int gbA = ((node0 + i0 + iA) << 7) + dbase;
    int gbB = ((node0 + i0 + iB) << 7) + dbase;
    {
        float4 xv = *(const float4*)(X + gbA);
        float4 o;
        o.x = xv.x + (afA[0] - muA) * invA * gv.x + bv.x + pA[0] * sc.x + sh.x;
        o.y = xv.y + (afA[1] - muA) * invA * gv.y + bv.y + pA[1] * sc.y + sh.y;
        o.z = xv.z + (afA[2] - muA) * invA * gv.z + bv.z + pA[2] * sc.z + sh.z;
        o.w = xv.w + (afA[3] - muA) * invA * gv.w + bv.w + pA[3] * sc.w + sh.w;
        *(float4*)(out + gbA) = o;
    }
    {
        float4 xv = *(const float4*)(X + gbB);
        float4 o;
        o.x = xv.x + (afB[0] - muB) * invB * gv.x + bv.x + pB[0] * sc.x + sh.x;
        o.y = xv.y + (afB[1] - muB) * invB * gv.y + bv.y + pB[1] * sc.y + sh.y;
        o.z = xv.z + (afB[2] - muB) * invB * gv.z + bv.z + pB[2] * sc.z + sh.z;
        o.w = xv.w + (afB[3] - muB) * invB * gv.w + bv.w + pB[3] * sc.w + sh.w;
        *(float4*)(out + gbB) = o;
    }

    // ---------------- reset tickets for next (graph-replayed) launch -------------
    if (tid == 0) {
        unsigned t2 = atomicAdd(&g_cnt2, 1u);
        if (t2 == 127u) {
            g_cnt  = 0u;
            g_cnt2 = 0u;
            g_flag = 0u;
        }
    }
}

// ============================================================================
extern "C" void kernel_launch(void* const* d_in, const int* in_sizes, int n_in,
                              void* d_out, int out_size) {
    const float* X    = (const float*)d_in[0];
    const float* XYZ  = (const float*)d_in[1];
    const float* Wxyz = (const float*)d_in[2];
    const float* bn_g = (const float*)d_in[3];
    const float* bn_b = (const float*)d_in[4];
    const float* W1   = (const float*)d_in[5];
    const float* b1   = (const float*)d_in[6];
    const float* ln_g = (const float*)d_in[7];
    const float* ln_b = (const float*)d_in[8];
    float* out = (float*)d_out;

    const int smem = SM_FLOATS * 4;   // 200192 B

    cudaFuncSetAttribute(mega, cudaFuncAttributeMaxDynamicSharedMemorySize, smem);

    mega<<<128, 1024, smem>>>(X, XYZ, Wxyz, bn_g, bn_b, W1, b1, ln_g, ln_b, out);
}

// round 13
// speedup vs baseline: 1.0598x; 1.0598x over previous
#include <cuda_runtime.h>
#include <cuda_bf16.h>
#include <math.h>

#define CLOUDS 64
#define PPC    128
#define DIM    128
#define NNODES (CLOUDS * PPC)
#define EPSV   1e-5f

typedef unsigned long long ull;

// ---------------- scratch ------------------------------------------------------
__device__ float g_Y[NNODES * DIM];     // X @ W1
__device__ float g_P2[NNODES * DIM];    // branch-2 pooled
__device__ float g_ps[128 * 128];
__device__ float g_pss[128 * 128];
__device__ float g_bstats[256];         // [0:128) scale, [128:256) shift
__device__ unsigned g_cnt;

// ---------------- helpers ------------------------------------------------------
__device__ __forceinline__ ull pack2(float lo, float hi) {
    ull r; asm("mov.b64 %0, {%1, %2};" : "=l"(r) : "f"(lo), "f"(hi)); return r;
}
__device__ __forceinline__ void unpack2(ull v, float& lo, float& hi) {
    asm("mov.b64 {%0, %1}, %2;" : "=f"(lo), "=f"(hi) : "l"(v));
}
__device__ __forceinline__ ull fma2(ull a, ull b, ull c) {
    ull d; asm("fma.rn.f32x2 %0, %1, %2, %3;" : "=l"(d) : "l"(a), "l"(b), "l"(c)); return d;
}
__device__ __forceinline__ ull add2(ull a, ull b) {
    ull d; asm("add.rn.f32x2 %0, %1, %2;" : "=l"(d) : "l"(a), "l"(b)); return d;
}
__device__ __forceinline__ float rsqrt_ap(float x) {
    float r; asm("rsqrt.approx.f32 %0, %1;" : "=f"(r) : "f"(x)); return r;
}
__device__ __forceinline__ float ex2_ap(float x) {
    float r; asm("ex2.approx.f32 %0, %1;" : "=f"(r) : "f"(x)); return r;
}

#define NEG1_2 0xBF800000BF800000ULL
#define LOG2E  1.4426950408889634f

// ============================================================================
// K0: Y = X @ W1.  Mega-style: 64 CTAs (one per cloud) x 1024 threads.
// Each CTA computes the full 128x128x128 cloud GEMM in two 64-k phases.
// 8 warps/SMSP; per warp per k: 4 bcast LDS.128 + 1 LDS.64 + 8 independent
// FFMA2.  smem 128 KB.
// ============================================================================
__global__ void __launch_bounds__(1024, 1)
k0_gemm(const float* __restrict__ X, const float* __restrict__ W1) {
    extern __shared__ ull sm0[];
    ull* wp = sm0;            // [128 k][64 cp]        (64 KB)
    ull* xd = sm0 + 8192;     // [64 k][128 r] dup     (64 KB)

    const int tid   = threadIdx.x;
    const int node0 = blockIdx.x << 7;

    // stage full W1 (64 KB)
    {
        const float4* W4 = (const float4*)W1;
        float4* d = (float4*)wp;
        #pragma unroll
        for (int t = 0; t < 4; t++) d[tid + t * 1024] = W4[tid + t * 1024];
    }

    const int rowg = tid >> 6;   // 0..15 (8 rows each; warp-uniform)
    const int cp   = tid & 63;

    ull acc[8];
    #pragma unroll
    for (int r = 0; r < 8; r++) acc[r] = 0ULL;

    #pragma unroll
    for (int ph = 0; ph < 2; ph++) {
        const int kb = ph * 64;
        // stage xd[k][r] = (x,x) for k in [kb, kb+64)
        {
            int r  = tid >> 3;          // 0..127
            int fq = tid & 7;           // 0..7
            const float4* X4 = (const float4*)X + (ull)(node0 + r) * 32 + (kb >> 2);
            #pragma unroll
            for (int h = 0; h < 2; h++) {
                int q = fq + h * 8;     // 0..15
                float4 v = X4[q];
                xd[(q * 4 + 0) * 128 + r] = pack2(v.x, v.x);
                xd[(q * 4 + 1) * 128 + r] = pack2(v.y, v.y);
                xd[(q * 4 + 2) * 128 + r] = pack2(v.z, v.z);
                xd[(q * 4 + 3) * 128 + r] = pack2(v.w, v.w);
            }
        }
        __syncthreads();
        #pragma unroll 4
        for (int k = 0; k < 64; k++) {
            const ulonglong2* xv = (const ulonglong2*)(xd + k * 128 + rowg * 8);
            ulonglong2 x0 = xv[0], x1 = xv[1], x2 = xv[2], x3 = xv[3];
            ull xr[8] = {x0.x, x0.y, x1.x, x1.y, x2.x, x2.y, x3.x, x3.y};
            ull wv = wp[(kb + k) * 64 + cp];
            #pragma unroll
            for (int r = 0; r < 8; r++) acc[r] = fma2(xr[r], wv, acc[r]);
        }
        __syncthreads();
    }

    #pragma unroll
    for (int r = 0; r < 8; r++)
        ((ull*)(g_Y + (ull)(node0 + rowg * 8 + r) * DIM))[cp] = acc[r];
}

// ============================================================================
// K2: branch 2 (unchanged).  Writes g_P2 + BN partials; last CTA -> g_bstats.
// ============================================================================
#define ST_STRIDE 132
__global__ void __launch_bounds__(512, 1)
k2_branch2(const float* __restrict__ XYZ, const float* __restrict__ Wxyz,
           const float* __restrict__ bn_g, const float* __restrict__ bn_b) {
    extern __shared__ float sm2[];
    float* zs   = sm2;                       // [128][128]       (16384 f)
    float* st   = sm2 + 16384;               // [64][132] stage  (8448 f)
    float* xyzs = sm2 + 16384 + 8448;        // [128][4]         (512 f)
    float* wxs  = xyzs + 512;                // [3][128]         (384 f)

    const int tid  = threadIdx.x;
    const int w    = tid >> 5;
    const int lane = tid & 31;
    const int i_l   = ((w & 1) << 5) | lane;
    const int dbase = (w >> 1) << 4;

    const int cta   = blockIdx.x;
    const int node0 = (cta >> 1) << 7;
    const int i0    = (cta & 1) << 6;

    if (tid < 128) {
        const float* p = XYZ + (node0 + tid) * 3;
        xyzs[tid * 4 + 0] = p[0];
        xyzs[tid * 4 + 1] = p[1];
        xyzs[tid * 4 + 2] = p[2];
        xyzs[tid * 4 + 3] = 0.f;
    }
    if (tid < 384) wxs[tid] = Wxyz[tid];
    __syncthreads();

    #pragma unroll
    for (int t = 0; t < 32; t++) {
        int idx = tid + t * 512;
        int jn = idx >> 7;
        int d  = idx & 127;
        zs[idx] = xyzs[(jn << 2) + 0] * wxs[d]
                + xyzs[(jn << 2) + 1] * wxs[128 + d]
                + xyzs[(jn << 2) + 2] * wxs[256 + d];
    }
    __syncthreads();

    ull zi[8];
    {
        const ull* zsu = (const ull*)zs;
        int zoff = (((i0 + i_l) << 7) + dbase) >> 1;
        #pragma unroll
        for (int p = 0; p < 8; p++) zi[p] = zsu[zoff + p];
    }
    ull acc[8];
    #pragma unroll
    for (int p = 0; p < 8; p++) acc[p] = 0ULL;

    #pragma unroll 4
    for (int j = 0; j < 128; j++) {
        const ulonglong2* zj2 = (const ulonglong2*)(zs + (j << 7) + dbase);
        ulonglong2 a0 = zj2[0], a1 = zj2[1], a2 = zj2[2], a3 = zj2[3];
        ull zj[8] = {a0.x, a0.y, a1.x, a1.y, a2.x, a2.y, a3.x, a3.y};
        #pragma unroll
        for (int p = 0; p < 8; p++) {
            ull df = fma2(zj[p], NEG1_2, zi[p]);
            float lo, hi;
            unpack2(df, lo, hi);
            lo = fmaxf(lo, 0.f);
            hi = fmaxf(hi, 0.f);
            acc[p] = add2(acc[p], pack2(lo, hi));
        }
    }

    float af[16];
    #pragma unroll
    for (int p = 0; p < 8; p++) unpack2(acc[p], af[2 * p], af[2 * p + 1]);
    #pragma unroll
    for (int q = 0; q < 4; q++) {
        float4 o;
        o.x = af[q * 4 + 0]; o.y = af[q * 4 + 1];
        o.z = af[q * 4 + 2]; o.w = af[q * 4 + 3];
        *(float4*)(st + i_l * ST_STRIDE + dbase + q * 4) = o;
    }
    __syncthreads();

    if (tid < 128) {
        float S = 0.f, SS = 0.f;
        #pragma unroll 8
        for (int i = 0; i < 64; i++) {
            float v = st[i * ST_STRIDE + tid];
            S += v; SS += v * v;
        }
        g_ps[cta * 128 + tid]  = S;
        g_pss[cta * 128 + tid] = SS;
    }
    const int nb = node0 + i0;
    #pragma unroll
    for (int t = 0; t < 16; t++) {
        int idx = tid + t * 512;
        int i = idx >> 7;
        int d = idx & 127;
        g_P2[((nb + i) << 7) + d] = st[i * ST_STRIDE + d];
    }

    // last-block: reduce partials -> g_bstats (deterministic fixed order)
    __shared__ unsigned s_tk;
    __threadfence();
    if (tid == 0) s_tk = atomicAdd(&g_cnt, 1u);
    __syncthreads();
    if (s_tk == 127u) {
        __threadfence();
        const int d   = tid & 127;
        const int grp = tid >> 7;
        const float* ps  = g_ps  + grp * 32 * 128 + d;
        const float* pss = g_pss + grp * 32 * 128 + d;
        float S = 0.f, SS = 0.f;
        #pragma unroll 8
        for (int c = 0; c < 32; c++) {
            S  += ps[c * 128];
            SS += pss[c * 128];
        }
        st[grp * 128 + d]       = S;
        st[512 + grp * 128 + d] = SS;
        __syncthreads();
        if (tid < 128) {
            float St  = st[tid] + st[128 + tid] + st[256 + tid] + st[384 + tid];
            float SSt = st[512 + tid] + st[640 + tid] + st[768 + tid] + st[896 + tid];
            float mu  = St * (1.f / (float)NNODES);
            float var = SSt * (1.f / (float)NNODES) - mu * mu;
            float inv = 1.f / sqrtf(var + EPSV);
            float scale = inv * bn_g[tid];
            g_bstats[tid]       = scale;
            g_bstats[128 + tid] = bn_b[tid] - mu * scale;
        }
        __threadfence();
        if (tid == 0) g_cnt = 0u;
    }
}

// ============================================================================
// K1: branch 1 + fused output (R10 mapping; reads single g_Y).
// 1024 threads = 32 warps; warp = i-pair, lane = d-chunk of 4 floats.
// ============================================================================
__global__ void __launch_bounds__(1024, 1)
k1_branch1(const float* __restrict__ X, const float* __restrict__ XYZ,
           const float* __restrict__ b1, const float* __restrict__ ln_g,
           const float* __restrict__ ln_b, float* __restrict__ out) {
    extern __shared__ float sm1[];
    float* ys   = sm1;            // [128][128]  (16384 f)
    float* ws   = sm1 + 16384;    // [128 j][64 i]  (8192 f)
    float* xyzs = sm1 + 24576;    // [128][4]    (512 f)

    const int tid  = threadIdx.x;
    const int w    = tid >> 5;
    const int lane = tid & 31;
    const int iA   = w << 1;
    const int iB   = iA + 1;
    const int dbase = lane << 2;

    const int cta   = blockIdx.x;
    const int node0 = (cta >> 1) << 7;
    const int i0    = (cta & 1) << 6;

    {
        const float4* Yv = (const float4*)(g_Y + node0 * DIM);
        float4* ysv = (float4*)ys;
        #pragma unroll
        for (int t = 0; t < 4; t++) ysv[tid + t * 1024] = Yv[tid + t * 1024];
    }
    if (tid < 128) {
        const float* p = XYZ + (node0 + tid) * 3;
        xyzs[tid * 4 + 0] = p[0];
        xyzs[tid * 4 + 1] = p[1];
        xyzs[tid * 4 + 2] = p[2];
        xyzs[tid * 4 + 3] = 0.f;
    }
    __syncthreads();

    #pragma unroll
    for (int t = 0; t < 8; t++) {
        int idx = tid + t * 1024;
        int ii = idx & 63;
        int jj = idx >> 6;
        float dx = xyzs[((i0 + ii) << 2) + 0] - xyzs[(jj << 2) + 0];
        float dy = xyzs[((i0 + ii) << 2) + 1] - xyzs[(jj << 2) + 1];
        float dz = xyzs[((i0 + ii) << 2) + 2] - xyzs[(jj << 2) + 2];
        float d2 = dx * dx + dy * dy + dz * dz;
        float dist = d2 * rsqrt_ap(fmaxf(d2, 1e-30f));
        ws[(jj << 6) + ii] = ex2_ap(-dist * LOG2E);
    }

    ull yiA[2], yiB[2], b1p[2];
    {
        const ull* b1u = (const ull*)b1;
        b1p[0] = b1u[lane * 2 + 0];
        b1p[1] = b1u[lane * 2 + 1];
    }
    __syncthreads();
    {
        const ull* ysu = (const ull*)ys;
        int offA = (i0 + iA) * 64 + lane * 2;
        int offB = (i0 + iB) * 64 + lane * 2;
        yiA[0] = ysu[offA]; yiA[1] = ysu[offA + 1];
        yiB[0] = ysu[offB]; yiB[1] = ysu[offB + 1];
    }
    ull accA[2] = {0ULL, 0ULL}, accB[2] = {0ULL, 0ULL};

    #pragma unroll 4
    for (int j = 0; j < 128; j++) {
        ull wv = *(const ull*)(ws + (j << 6) + iA);
        float w0, w1;
        unpack2(wv, w0, w1);
        ull w20 = pack2(w0, w0);
        ull w21 = pack2(w1, w1);
        ulonglong2 yj = *(const ulonglong2*)(ys + (j << 7) + dbase);
        ull yjp[2] = {yj.x, yj.y};
        #pragma unroll
        for (int p = 0; p < 2; p++) {
            ull df = fma2(yjp[p], NEG1_2, yiA[p]);
            ull t  = fma2(w20, df, b1p[p]);
            float lo, hi;
            unpack2(t, lo, hi);
            lo = fmaxf(lo, 0.f); hi = fmaxf(hi, 0.f);
            accA[p] = add2(accA[p], pack2(lo, hi));

            df = fma2(yjp[p], NEG1_2, yiB[p]);
            t  = fma2(w21, df, b1p[p]);
            unpack2(t, lo, hi);
            lo = fmaxf(lo, 0.f); hi = fmaxf(hi, 0.f);
            accB[p] = add2(accB[p], pack2(lo, hi));
        }
    }

    float afA[4], afB[4];
    #pragma unroll
    for (int p = 0; p < 2; p++) {
        float bl, bh; unpack2(b1p[p], bl, bh);
        float rb0 = fmaxf(bl, 0.f), rb1 = fmaxf(bh, 0.f);
        float lo, hi;
        unpack2(accA[p], lo, hi);
        afA[2 * p + 0] = lo - rb0;
        afA[2 * p + 1] = hi - rb1;
        unpack2(accB[p], lo, hi);
        afB[2 * p + 0] = lo - rb0;
        afB[2 * p + 1] = hi - rb1;
    }
    float sA = 0.f, qA = 0.f, sB = 0.f, qB = 0.f;
    #pragma unroll
    for (int k = 0; k < 4; k++) {
        sA += afA[k]; qA += afA[k] * afA[k];
        sB += afB[k]; qB += afB[k] * afB[k];
    }
    #pragma unroll
    for (int off = 16; off > 0; off >>= 1) {
        sA += __shfl_xor_sync(0xffffffffu, sA, off);
        qA += __shfl_xor_sync(0xffffffffu, qA, off);
        sB += __shfl_xor_sync(0xffffffffu, sB, off);
        qB += __shfl_xor_sync(0xffffffffu, qB, off);
    }
    float muA  = sA * (1.f / 128.f);
    float invA = 1.f / sqrtf(qA * (1.f / 128.f) - muA * muA + EPSV);
    float muB  = sB * (1.f / 128.f);
    float invB = 1.f / sqrtf(qB * (1.f / 128.f) - muB * muB + EPSV);

    float4 gv = *(const float4*)(ln_g + dbase);
    float4 bv = *(const float4*)(ln_b + dbase);
    float4 sc = *(const float4*)(g_bstats + dbase);
    float4 sh = *(const float4*)(g_bstats + 128 + dbase);

    int gbA = ((node0 + i0 + iA) << 7) + dbase;
    int gbB = ((node0 + i0 + iB) << 7) + dbase;
    {
        float4 xv = *(const float4*)(X + gbA);
        float4 pv = *(const float4*)(g_P2 + gbA);
        float4 o;
        o.x = xv.x + (afA[0] - muA) * invA * gv.x + bv.x + pv.x * sc.x + sh.x;
        o.y = xv.y + (afA[1] - muA) * invA * gv.y + bv.y + pv.y * sc.y + sh.y;
        o.z = xv.z + (afA[2] - muA) * invA * gv.z + bv.z + pv.z * sc.z + sh.z;
        o.w = xv.w + (afA[3] - muA) * invA * gv.w + bv.w + pv.w * sc.w + sh.w;
        *(float4*)(out + gbA) = o;
    }
    {
        float4 xv = *(const float4*)(X + gbB);
        float4 pv = *(const float4*)(g_P2 + gbB);
        float4 o;
        o.x = xv.x + (afB[0] - muB) * invB * gv.x + bv.x + pv.x * sc.x + sh.x;
        o.y = xv.y + (afB[1] - muB) * invB * gv.y + bv.y + pv.y * sc.y + sh.y;
        o.z = xv.z + (afB[2] - muB) * invB * gv.z + bv.z + pv.z * sc.z + sh.z;
        o.w = xv.w + (afB[3] - muB) * invB * gv.w + bv.w + pv.w * sc.w + sh.w;
        *(float4*)(out + gbB) = o;
    }
}

// ============================================================================
extern "C" void kernel_launch(void* const* d_in, const int* in_sizes, int n_in,
                              void* d_out, int out_size) {
    const float* X    = (const float*)d_in[0];
    const float* XYZ  = (const float*)d_in[1];
    const float* Wxyz = (const float*)d_in[2];
    const float* bn_g = (const float*)d_in[3];
    const float* bn_b = (const float*)d_in[4];
    const float* W1   = (const float*)d_in[5];
    const float* b1   = (const float*)d_in[6];
    const float* ln_g = (const float*)d_in[7];
    const float* ln_b = (const float*)d_in[8];
    float* out = (float*)d_out;

    const int smem0 = 16384 * 8;                               // 128 KB
    const int smem1 = (16384 + 8192 + 512) * 4;                // ~100.4 KB
    const int smem2 = (16384 + 8448 + 512 + 384) * 4;          // ~102.9 KB

    cudaFuncSetAttribute(k0_gemm,    cudaFuncAttributeMaxDynamicSharedMemorySize, smem0);
    cudaFuncSetAttribute(k1_branch1, cudaFuncAttributeMaxDynamicSharedMemorySize, smem1);
    cudaFuncSetAttribute(k2_branch2, cudaFuncAttributeMaxDynamicSharedMemorySize, smem2);

    // Fork-join: k0 (legacy stream) || k2 (forked stream); k1 joins.
    cudaStream_t s1;
    cudaStreamCreateWithFlags(&s1, cudaStreamNonBlocking);
    cudaEvent_t evA, evB;
    cudaEventCreateWithFlags(&evA, cudaEventDisableTiming);
    cudaEventCreateWithFlags(&evB, cudaEventDisableTiming);

    cudaEventRecord(evA, 0);
    cudaStreamWaitEvent(s1, evA, 0);

    k0_gemm   <<<64, 1024, smem0>>>(X, W1);                     // legacy stream
    k2_branch2<<<128, 512, smem2, s1>>>(XYZ, Wxyz, bn_g, bn_b); // forked stream

    cudaEventRecord(evB, s1);
    cudaStreamWaitEvent(0, evB, 0);

    k1_branch1<<<128, 1024, smem1>>>(X, XYZ, b1, ln_g, ln_b, out);
}

// round 14
// speedup vs baseline: 1.1510x; 1.0861x over previous
#include <cuda_runtime.h>
#include <cuda_bf16.h>
#include <math.h>

#define CLOUDS 64
#define PPC    128
#define DIM    128
#define NNODES (CLOUDS * PPC)
#define EPSV   1e-5f

typedef unsigned long long ull;

// ---------------- scratch ------------------------------------------------------
__device__ float g_Y[NNODES * DIM];     // X @ W1
__device__ float g_P2[NNODES * DIM];    // branch-2 pooled
__device__ float g_ps[128 * 128];
__device__ float g_pss[128 * 128];
__device__ float g_bstats[256];         // [0:128) scale, [128:256) shift
__device__ unsigned g_cnt;

// ---------------- helpers ------------------------------------------------------
__device__ __forceinline__ ull pack2(float lo, float hi) {
    ull r; asm("mov.b64 %0, {%1, %2};" : "=l"(r) : "f"(lo), "f"(hi)); return r;
}
__device__ __forceinline__ void unpack2(ull v, float& lo, float& hi) {
    asm("mov.b64 {%0, %1}, %2;" : "=f"(lo), "=f"(hi) : "l"(v));
}
__device__ __forceinline__ ull fma2(ull a, ull b, ull c) {
    ull d; asm("fma.rn.f32x2 %0, %1, %2, %3;" : "=l"(d) : "l"(a), "l"(b), "l"(c)); return d;
}
__device__ __forceinline__ ull add2(ull a, ull b) {
    ull d; asm("add.rn.f32x2 %0, %1, %2;" : "=l"(d) : "l"(a), "l"(b)); return d;
}
__device__ __forceinline__ float rsqrt_ap(float x) {
    float r; asm("rsqrt.approx.f32 %0, %1;" : "=f"(r) : "f"(x)); return r;
}
__device__ __forceinline__ float ex2_ap(float x) {
    float r; asm("ex2.approx.f32 %0, %1;" : "=f"(r) : "f"(x)); return r;
}

#define NEG1_2 0xBF800000BF800000ULL
#define LOG2E  1.4426950408889634f

// ============================================================================
// K0: Y = X @ W1  (R6's best-measured shape: 128 CTAs x 256 threads, 64 rows
// per CTA, full k in smem, 8 warps, thread = 8 rows x 2 col-pairs).
// ============================================================================
__global__ void __launch_bounds__(256, 1)
k0_gemm(const float* __restrict__ X, const float* __restrict__ W1) {
    extern __shared__ ull sm0[];
    ull* wp = sm0;            // [128 k][64 col-pairs]  (64 KB)
    ull* xd = sm0 + 8192;     // [128 k][64 rows] dup (v,v)  (64 KB)

    const int tid = threadIdx.x;
    const int r0  = blockIdx.x * 64;

    const float4* w4 = (const float4*)W1;
    float4* wps = (float4*)wp;
    #pragma unroll
    for (int t = 0; t < 16; t++) wps[tid + t * 256] = w4[tid + t * 256];

    #pragma unroll
    for (int t = 0; t < 32; t++) {
        int idx = tid + t * 256;
        int r = idx & 63;
        int k = idx >> 6;
        float v = X[(r0 + r) * DIM + k];
        xd[k * 64 + r] = pack2(v, v);
    }
    __syncthreads();

    const int rb = tid >> 5;   // warp-uniform row block (broadcast LDS)
    const int cb = tid & 31;   // 32 col-blocks of 2 pairs

    ull acc[8][2];
    #pragma unroll
    for (int r = 0; r < 8; r++) { acc[r][0] = 0ULL; acc[r][1] = 0ULL; }

    #pragma unroll 4
    for (int k = 0; k < 128; k++) {
        const ulonglong2* xv = (const ulonglong2*)(xd + k * 64 + rb * 8);
        ulonglong2 x0 = xv[0], x1 = xv[1], x2 = xv[2], x3 = xv[3];
        ull xr[8] = {x0.x, x0.y, x1.x, x1.y, x2.x, x2.y, x3.x, x3.y};
        ulonglong2 wv = *(const ulonglong2*)(wp + k * 64 + cb * 2);
        #pragma unroll
        for (int r = 0; r < 8; r++) {
            acc[r][0] = fma2(xr[r], wv.x, acc[r][0]);
            acc[r][1] = fma2(xr[r], wv.y, acc[r][1]);
        }
    }

    #pragma unroll
    for (int r = 0; r < 8; r++) {
        int row = r0 + rb * 8 + r;
        float a, b, c, d;
        unpack2(acc[r][0], a, b);
        unpack2(acc[r][1], c, d);
        float4 o; o.x = a; o.y = b; o.z = c; o.w = d;
        ((float4*)(g_Y + row * DIM))[cb] = o;
    }
}

// ============================================================================
// K2: branch 2 (unchanged).  Writes g_P2 + BN partials; last CTA -> g_bstats.
// ============================================================================
#define ST_STRIDE 132
__global__ void __launch_bounds__(512, 1)
k2_branch2(const float* __restrict__ XYZ, const float* __restrict__ Wxyz,
           const float* __restrict__ bn_g, const float* __restrict__ bn_b) {
    extern __shared__ float sm2[];
    float* zs   = sm2;                       // [128][128]       (16384 f)
    float* st   = sm2 + 16384;               // [64][132] stage  (8448 f)
    float* xyzs = sm2 + 16384 + 8448;        // [128][4]         (512 f)
    float* wxs  = xyzs + 512;                // [3][128]         (384 f)

    const int tid  = threadIdx.x;
    const int w    = tid >> 5;
    const int lane = tid & 31;
    const int i_l   = ((w & 1) << 5) | lane;
    const int dbase = (w >> 1) << 4;

    const int cta   = blockIdx.x;
    const int node0 = (cta >> 1) << 7;
    const int i0    = (cta & 1) << 6;

    if (tid < 128) {
        const float* p = XYZ + (node0 + tid) * 3;
        xyzs[tid * 4 + 0] = p[0];
        xyzs[tid * 4 + 1] = p[1];
        xyzs[tid * 4 + 2] = p[2];
        xyzs[tid * 4 + 3] = 0.f;
    }
    if (tid < 384) wxs[tid] = Wxyz[tid];
    __syncthreads();

    #pragma unroll
    for (int t = 0; t < 32; t++) {
        int idx = tid + t * 512;
        int jn = idx >> 7;
        int d  = idx & 127;
        zs[idx] = xyzs[(jn << 2) + 0] * wxs[d]
                + xyzs[(jn << 2) + 1] * wxs[128 + d]
                + xyzs[(jn << 2) + 2] * wxs[256 + d];
    }
    __syncthreads();

    ull zi[8];
    {
        const ull* zsu = (const ull*)zs;
        int zoff = (((i0 + i_l) << 7) + dbase) >> 1;
        #pragma unroll
        for (int p = 0; p < 8; p++) zi[p] = zsu[zoff + p];
    }
    ull acc[8];
    #pragma unroll
    for (int p = 0; p < 8; p++) acc[p] = 0ULL;

    #pragma unroll 4
    for (int j = 0; j < 128; j++) {
        const ulonglong2* zj2 = (const ulonglong2*)(zs + (j << 7) + dbase);
        ulonglong2 a0 = zj2[0], a1 = zj2[1], a2 = zj2[2], a3 = zj2[3];
        ull zj[8] = {a0.x, a0.y, a1.x, a1.y, a2.x, a2.y, a3.x, a3.y};
        #pragma unroll
        for (int p = 0; p < 8; p++) {
            ull df = fma2(zj[p], NEG1_2, zi[p]);
            float lo, hi;
            unpack2(df, lo, hi);
            lo = fmaxf(lo, 0.f);
            hi = fmaxf(hi, 0.f);
            acc[p] = add2(acc[p], pack2(lo, hi));
        }
    }

    float af[16];
    #pragma unroll
    for (int p = 0; p < 8; p++) unpack2(acc[p], af[2 * p], af[2 * p + 1]);
    #pragma unroll
    for (int q = 0; q < 4; q++) {
        float4 o;
        o.x = af[q * 4 + 0]; o.y = af[q * 4 + 1];
        o.z = af[q * 4 + 2]; o.w = af[q * 4 + 3];
        *(float4*)(st + i_l * ST_STRIDE + dbase + q * 4) = o;
    }
    __syncthreads();

    if (tid < 128) {
        float S = 0.f, SS = 0.f;
        #pragma unroll 8
        for (int i = 0; i < 64; i++) {
            float v = st[i * ST_STRIDE + tid];
            S += v; SS += v * v;
        }
        g_ps[cta * 128 + tid]  = S;
        g_pss[cta * 128 + tid] = SS;
    }
    const int nb = node0 + i0;
    #pragma unroll
    for (int t = 0; t < 16; t++) {
        int idx = tid + t * 512;
        int i = idx >> 7;
        int d = idx & 127;
        g_P2[((nb + i) << 7) + d] = st[i * ST_STRIDE + d];
    }

    // last-block: reduce partials -> g_bstats (deterministic fixed order)
    __shared__ unsigned s_tk;
    __threadfence();
    if (tid == 0) s_tk = atomicAdd(&g_cnt, 1u);
    __syncthreads();
    if (s_tk == 127u) {
        __threadfence();
        const int d   = tid & 127;
        const int grp = tid >> 7;
        const float* ps  = g_ps  + grp * 32 * 128 + d;
        const float* pss = g_pss + grp * 32 * 128 + d;
        float S = 0.f, SS = 0.f;
        #pragma unroll 8
        for (int c = 0; c < 32; c++) {
            S  += ps[c * 128];
            SS += pss[c * 128];
        }
        st[grp * 128 + d]       = S;
        st[512 + grp * 128 + d] = SS;
        __syncthreads();
        if (tid < 128) {
            float St  = st[tid] + st[128 + tid] + st[256 + tid] + st[384 + tid];
            float SSt = st[512 + tid] + st[640 + tid] + st[768 + tid] + st[896 + tid];
            float mu  = St * (1.f / (float)NNODES);
            float var = SSt * (1.f / (float)NNODES) - mu * mu;
            float inv = 1.f / sqrtf(var + EPSV);
            float scale = inv * bn_g[tid];
            g_bstats[tid]       = scale;
            g_bstats[128 + tid] = bn_b[tid] - mu * scale;
        }
        __threadfence();
        if (tid == 0) g_cnt = 0u;
    }
}

// ============================================================================
// K1: branch 1 + fused output.  1024 threads = 32 warps; warp = i-pair,
// lane = d-chunk of 4.  Edge weights stored PRE-DUPLICATED as (w,w) ull pairs
// so the inner loop is: 1 bcast ulonglong2 (both nodes' w) + 1 distinct
// ulonglong2 (y_j chunk) + pure packed math.
// ============================================================================
__global__ void __launch_bounds__(1024, 1)
k1_branch1(const float* __restrict__ X, const float* __restrict__ XYZ,
           const float* __restrict__ b1, const float* __restrict__ ln_g,
           const float* __restrict__ ln_b, float* __restrict__ out) {
    extern __shared__ float sm1[];
    float* ys   = sm1;                  // [128][128]          (16384 f)
    ull*   ysu  = (ull*)ys;
    ull*   wsd  = (ull*)(sm1 + 16384);  // [128 j][64 i] (w,w) (16384 f)
    float* xyzs = sm1 + 32768;          // [128][4]            (512 f)

    const int tid  = threadIdx.x;
    const int w    = tid >> 5;
    const int lane = tid & 31;
    const int iA   = w << 1;
    const int iB   = iA + 1;
    const int dbase = lane << 2;

    const int cta   = blockIdx.x;
    const int node0 = (cta >> 1) << 7;
    const int i0    = (cta & 1) << 6;

    {
        const float4* Yv = (const float4*)(g_Y + node0 * DIM);
        float4* ysv = (float4*)ys;
        #pragma unroll
        for (int t = 0; t < 4; t++) ysv[tid + t * 1024] = Yv[tid + t * 1024];
    }
    if (tid < 128) {
        const float* p = XYZ + (node0 + tid) * 3;
        xyzs[tid * 4 + 0] = p[0];
        xyzs[tid * 4 + 1] = p[1];
        xyzs[tid * 4 + 2] = p[2];
        xyzs[tid * 4 + 3] = 0.f;
    }
    __syncthreads();

    // wsd[j*64 + i] = (w_ij, w_ij); diag -> (1,1) (finite; corrected in epilogue)
    #pragma unroll
    for (int t = 0; t < 8; t++) {
        int idx = tid + t * 1024;
        int ii = idx & 63;
        int jj = idx >> 6;
        float dx = xyzs[((i0 + ii) << 2) + 0] - xyzs[(jj << 2) + 0];
        float dy = xyzs[((i0 + ii) << 2) + 1] - xyzs[(jj << 2) + 1];
        float dz = xyzs[((i0 + ii) << 2) + 2] - xyzs[(jj << 2) + 2];
        float d2 = dx * dx + dy * dy + dz * dz;
        float dist = d2 * rsqrt_ap(fmaxf(d2, 1e-30f));
        float wv = ex2_ap(-dist * LOG2E);
        wsd[(jj << 6) + ii] = pack2(wv, wv);
    }

    ull yiA[2], yiB[2], b1p[2];
    {
        const ull* b1u = (const ull*)b1;
        b1p[0] = b1u[lane * 2 + 0];
        b1p[1] = b1u[lane * 2 + 1];
    }
    __syncthreads();
    {
        int offA = (i0 + iA) * 64 + lane * 2;
        int offB = (i0 + iB) * 64 + lane * 2;
        yiA[0] = ysu[offA]; yiA[1] = ysu[offA + 1];
        yiB[0] = ysu[offB]; yiB[1] = ysu[offB + 1];
    }
    ull accA[2] = {0ULL, 0ULL}, accB[2] = {0ULL, 0ULL};

    #pragma unroll 4
    for (int j = 0; j < 128; j++) {
        ulonglong2 wv2 = *(const ulonglong2*)(wsd + (j << 6) + iA); // (wA,wA),(wB,wB)
        ulonglong2 yj  = *(const ulonglong2*)(ysu + (j << 6) + lane * 2);
        ull yjp[2] = {yj.x, yj.y};
        #pragma unroll
        for (int p = 0; p < 2; p++) {
            float lo, hi;
            ull df = fma2(yjp[p], NEG1_2, yiA[p]);
            ull t  = fma2(wv2.x, df, b1p[p]);
            unpack2(t, lo, hi);
            lo = fmaxf(lo, 0.f); hi = fmaxf(hi, 0.f);
            accA[p] = add2(accA[p], pack2(lo, hi));

            df = fma2(yjp[p], NEG1_2, yiB[p]);
            t  = fma2(wv2.y, df, b1p[p]);
            unpack2(t, lo, hi);
            lo = fmaxf(lo, 0.f); hi = fmaxf(hi, 0.f);
            accB[p] = add2(accB[p], pack2(lo, hi));
        }
    }

    float afA[4], afB[4];
    #pragma unroll
    for (int p = 0; p < 2; p++) {
        float bl, bh; unpack2(b1p[p], bl, bh);
        float rb0 = fmaxf(bl, 0.f), rb1 = fmaxf(bh, 0.f);
        float lo, hi;
        unpack2(accA[p], lo, hi);
        afA[2 * p + 0] = lo - rb0;
        afA[2 * p + 1] = hi - rb1;
        unpack2(accB[p], lo, hi);
        afB[2 * p + 0] = lo - rb0;
        afB[2 * p + 1] = hi - rb1;
    }
    float sA = 0.f, qA = 0.f, sB = 0.f, qB = 0.f;
    #pragma unroll
    for (int k = 0; k < 4; k++) {
        sA += afA[k]; qA += afA[k] * afA[k];
        sB += afB[k]; qB += afB[k] * afB[k];
    }
    #pragma unroll
    for (int off = 16; off > 0; off >>= 1) {
        sA += __shfl_xor_sync(0xffffffffu, sA, off);
        qA += __shfl_xor_sync(0xffffffffu, qA, off);
        sB += __shfl_xor_sync(0xffffffffu, sB, off);
        qB += __shfl_xor_sync(0xffffffffu, qB, off);
    }
    float muA  = sA * (1.f / 128.f);
    float invA = 1.f / sqrtf(qA * (1.f / 128.f) - muA * muA + EPSV);
    float muB  = sB * (1.f / 128.f);
    float invB = 1.f / sqrtf(qB * (1.f / 128.f) - muB * muB + EPSV);

    float4 gv = *(const float4*)(ln_g + dbase);
    float4 bv = *(const float4*)(ln_b + dbase);
    float4 sc = *(const float4*)(g_bstats + dbase);
    float4 sh = *(const float4*)(g_bstats + 128 + dbase);

    int gbA = ((node0 + i0 + iA) << 7) + dbase;
    int gbB = ((node0 + i0 + iB) << 7) + dbase;
    {
        float4 xv = *(const float4*)(X + gbA);
        float4 pv = *(const float4*)(g_P2 + gbA);
        float4 o;
        o.x = xv.x + (afA[0] - muA) * invA * gv.x + bv.x + pv.x * sc.x + sh.x;
        o.y = xv.y + (afA[1] - muA) * invA * gv.y + bv.y + pv.y * sc.y + sh.y;
        o.z = xv.z + (afA[2] - muA) * invA * gv.z + bv.z + pv.z * sc.z + sh.z;
        o.w = xv.w + (afA[3] - muA) * invA * gv.w + bv.w + pv.w * sc.w + sh.w;
        *(float4*)(out + gbA) = o;
    }
    {
        float4 xv = *(const float4*)(X + gbB);
        float4 pv = *(const float4*)(g_P2 + gbB);
        float4 o;
        o.x = xv.x + (afB[0] - muB) * invB * gv.x + bv.x + pv.x * sc.x + sh.x;
        o.y = xv.y + (afB[1] - muB) * invB * gv.y + bv.y + pv.y * sc.y + sh.y;
        o.z = xv.z + (afB[2] - muB) * invB * gv.z + bv.z + pv.z * sc.z + sh.z;
        o.w = xv.w + (afB[3] - muB) * invB * gv.w + bv.w + pv.w * sc.w + sh.w;
        *(float4*)(out + gbB) = o;
    }
}

// ============================================================================
extern "C" void kernel_launch(void* const* d_in, const int* in_sizes, int n_in,
                              void* d_out, int out_size) {
    const float* X    = (const float*)d_in[0];
    const float* XYZ  = (const float*)d_in[1];
    const float* Wxyz = (const float*)d_in[2];
    const float* bn_g = (const float*)d_in[3];
    const float* bn_b = (const float*)d_in[4];
    const float* W1   = (const float*)d_in[5];
    const float* b1   = (const float*)d_in[6];
    const float* ln_g = (const float*)d_in[7];
    const float* ln_b = (const float*)d_in[8];
    float* out = (float*)d_out;

    const int smem0 = 16384 * 8;                               // 128 KB
    const int smem1 = (16384 + 16384 + 512) * 4;               // ~130 KB
    const int smem2 = (16384 + 8448 + 512 + 384) * 4;          // ~102.9 KB

    cudaFuncSetAttribute(k0_gemm,    cudaFuncAttributeMaxDynamicSharedMemorySize, smem0);
    cudaFuncSetAttribute(k1_branch1, cudaFuncAttributeMaxDynamicSharedMemorySize, smem1);
    cudaFuncSetAttribute(k2_branch2, cudaFuncAttributeMaxDynamicSharedMemorySize, smem2);

    // Fork-join: k0 (legacy stream) || k2 (forked stream); k1 joins.
    cudaStream_t s1;
    cudaStreamCreateWithFlags(&s1, cudaStreamNonBlocking);
    cudaEvent_t evA, evB;
    cudaEventCreateWithFlags(&evA, cudaEventDisableTiming);
    cudaEventCreateWithFlags(&evB, cudaEventDisableTiming);

    cudaEventRecord(evA, 0);
    cudaStreamWaitEvent(s1, evA, 0);

    k0_gemm   <<<128, 256, smem0>>>(X, W1);                     // legacy stream
    k2_branch2<<<128, 512, smem2, s1>>>(XYZ, Wxyz, bn_g, bn_b); // forked stream

    cudaEventRecord(evB, s1);
    cudaStreamWaitEvent(0, evB, 0);

    k1_branch1<<<128, 1024, smem1>>>(X, XYZ, b1, ln_g, ln_b, out);
}

// round 15
// speedup vs baseline: 1.2422x; 1.0792x over previous
#include <cuda_runtime.h>
#include <cuda_bf16.h>
#include <mma.h>
#include <math.h>

using namespace nvcuda;

#define CLOUDS 64
#define PPC    128
#define DIM    128
#define NNODES (CLOUDS * PPC)
#define EPSV   1e-5f

typedef unsigned long long ull;

// ---------------- scratch ------------------------------------------------------
__device__ float g_Y[NNODES * DIM];     // X @ W1
__device__ float g_P2[NNODES * DIM];    // branch-2 pooled
__device__ float g_ps[128 * 128];
__device__ float g_pss[128 * 128];
__device__ float g_bstats[256];         // [0:128) scale, [128:256) shift
__device__ unsigned g_cnt;

// ---------------- helpers ------------------------------------------------------
__device__ __forceinline__ ull pack2(float lo, float hi) {
    ull r; asm("mov.b64 %0, {%1, %2};" : "=l"(r) : "f"(lo), "f"(hi)); return r;
}
__device__ __forceinline__ void unpack2(ull v, float& lo, float& hi) {
    asm("mov.b64 {%0, %1}, %2;" : "=f"(lo), "=f"(hi) : "l"(v));
}
__device__ __forceinline__ ull fma2(ull a, ull b, ull c) {
    ull d; asm("fma.rn.f32x2 %0, %1, %2, %3;" : "=l"(d) : "l"(a), "l"(b), "l"(c)); return d;
}
__device__ __forceinline__ ull add2(ull a, ull b) {
    ull d; asm("add.rn.f32x2 %0, %1, %2;" : "=l"(d) : "l"(a), "l"(b)); return d;
}
__device__ __forceinline__ float rsqrt_ap(float x) {
    float r; asm("rsqrt.approx.f32 %0, %1;" : "=f"(r) : "f"(x)); return r;
}
__device__ __forceinline__ float ex2_ap(float x) {
    float r; asm("ex2.approx.f32 %0, %1;" : "=f"(r) : "f"(x)); return r;
}

#define NEG1_2 0xBF800000BF800000ULL
#define LOG2E  1.4426950408889634f

// ============================================================================
// K0: Y = X @ W1 on TENSOR CORES.  Split-bf16, 3 terms:
//   Y = Xhi@Whi + Xhi@Wlo + Xlo@Whi   (fp32 accumulate, err ~3e-5)
// 128 CTAs x 256 thr; CTA = 64 rows x 128 cols; warp = 16 rows x 64 cols.
// smem: bf16 Whi/Wlo [128][136] + Xhi/Xlo [64][136]  (~102 KB).
// ============================================================================
#define LDB 136   // padded bf16 row stride (272 B, 16B-aligned)

__global__ void __launch_bounds__(256, 1)
k0_gemm(const float* __restrict__ X, const float* __restrict__ W1) {
    extern __shared__ __nv_bfloat16 smb[];
    __nv_bfloat16* Whi = smb;                       // [128][136]
    __nv_bfloat16* Wlo = smb + 128 * LDB;           // [128][136]
    __nv_bfloat16* Xhi = smb + 2 * 128 * LDB;       // [64][136]
    __nv_bfloat16* Xlo = Xhi + 64 * LDB;            // [64][136]

    const int tid = threadIdx.x;
    const int r0  = blockIdx.x * 64;

    // convert W1 (16384 elems) to hi/lo bf16
    #pragma unroll
    for (int t = 0; t < 64; t++) {
        int idx = tid + t * 256;
        int r = idx >> 7, c = idx & 127;
        float v = W1[idx];
        __nv_bfloat16 h = __float2bfloat16(v);
        Whi[r * LDB + c] = h;
        Wlo[r * LDB + c] = __float2bfloat16(v - __bfloat162float(h));
    }
    // convert X rows [r0, r0+64)
    #pragma unroll
    for (int t = 0; t < 32; t++) {
        int idx = tid + t * 256;
        int r = idx >> 7, c = idx & 127;
        float v = X[(r0 + r) * DIM + c];
        __nv_bfloat16 h = __float2bfloat16(v);
        Xhi[r * LDB + c] = h;
        Xlo[r * LDB + c] = __float2bfloat16(v - __bfloat162float(h));
    }
    __syncthreads();

    const int wid = tid >> 5;
    const int rw  = wid >> 1;     // 0..3  row group (16 rows)
    const int cw  = wid & 1;      // 0..1  col group (64 cols)

    wmma::fragment<wmma::accumulator, 16, 16, 16, float> acc[4];
    #pragma unroll
    for (int c = 0; c < 4; c++) wmma::fill_fragment(acc[c], 0.f);

    #pragma unroll
    for (int ks = 0; ks < 8; ks++) {
        wmma::fragment<wmma::matrix_a, 16, 16, 16, __nv_bfloat16, wmma::row_major> ahi, alo;
        wmma::load_matrix_sync(ahi, Xhi + rw * 16 * LDB + ks * 16, LDB);
        wmma::load_matrix_sync(alo, Xlo + rw * 16 * LDB + ks * 16, LDB);
        #pragma unroll
        for (int c = 0; c < 4; c++) {
            wmma::fragment<wmma::matrix_b, 16, 16, 16, __nv_bfloat16, wmma::row_major> bhi, blo;
            int col = cw * 64 + c * 16;
            wmma::load_matrix_sync(bhi, Whi + ks * 16 * LDB + col, LDB);
            wmma::load_matrix_sync(blo, Wlo + ks * 16 * LDB + col, LDB);
            wmma::mma_sync(acc[c], ahi, bhi, acc[c]);
            wmma::mma_sync(acc[c], ahi, blo, acc[c]);
            wmma::mma_sync(acc[c], alo, bhi, acc[c]);
        }
    }

    #pragma unroll
    for (int c = 0; c < 4; c++) {
        wmma::store_matrix_sync(g_Y + (ull)(r0 + rw * 16) * DIM + cw * 64 + c * 16,
                                acc[c], DIM, wmma::mem_row_major);
    }
}

// ============================================================================
// K2: branch 2 (unchanged).  Writes g_P2 + BN partials; last CTA -> g_bstats.
// ============================================================================
#define ST_STRIDE 132
__global__ void __launch_bounds__(512, 1)
k2_branch2(const float* __restrict__ XYZ, const float* __restrict__ Wxyz,
           const float* __restrict__ bn_g, const float* __restrict__ bn_b) {
    extern __shared__ float sm2[];
    float* zs   = sm2;                       // [128][128]       (16384 f)
    float* st   = sm2 + 16384;               // [64][132] stage  (8448 f)
    float* xyzs = sm2 + 16384 + 8448;        // [128][4]         (512 f)
    float* wxs  = xyzs + 512;                // [3][128]         (384 f)

    const int tid  = threadIdx.x;
    const int w    = tid >> 5;
    const int lane = tid & 31;
    const int i_l   = ((w & 1) << 5) | lane;
    const int dbase = (w >> 1) << 4;

    const int cta   = blockIdx.x;
    const int node0 = (cta >> 1) << 7;
    const int i0    = (cta & 1) << 6;

    if (tid < 128) {
        const float* p = XYZ + (node0 + tid) * 3;
        xyzs[tid * 4 + 0] = p[0];
        xyzs[tid * 4 + 1] = p[1];
        xyzs[tid * 4 + 2] = p[2];
        xyzs[tid * 4 + 3] = 0.f;
    }
    if (tid < 384) wxs[tid] = Wxyz[tid];
    __syncthreads();

    #pragma unroll
    for (int t = 0; t < 32; t++) {
        int idx = tid + t * 512;
        int jn = idx >> 7;
        int d  = idx & 127;
        zs[idx] = xyzs[(jn << 2) + 0] * wxs[d]
                + xyzs[(jn << 2) + 1] * wxs[128 + d]
                + xyzs[(jn << 2) + 2] * wxs[256 + d];
    }
    __syncthreads();

    ull zi[8];
    {
        const ull* zsu = (const ull*)zs;
        int zoff = (((i0 + i_l) << 7) + dbase) >> 1;
        #pragma unroll
        for (int p = 0; p < 8; p++) zi[p] = zsu[zoff + p];
    }
    ull acc[8];
    #pragma unroll
    for (int p = 0; p < 8; p++) acc[p] = 0ULL;

    #pragma unroll 4
    for (int j = 0; j < 128; j++) {
        const ulonglong2* zj2 = (const ulonglong2*)(zs + (j << 7) + dbase);
        ulonglong2 a0 = zj2[0], a1 = zj2[1], a2 = zj2[2], a3 = zj2[3];
        ull zj[8] = {a0.x, a0.y, a1.x, a1.y, a2.x, a2.y, a3.x, a3.y};
        #pragma unroll
        for (int p = 0; p < 8; p++) {
            ull df = fma2(zj[p], NEG1_2, zi[p]);
            float lo, hi;
            unpack2(df, lo, hi);
            lo = fmaxf(lo, 0.f);
            hi = fmaxf(hi, 0.f);
            acc[p] = add2(acc[p], pack2(lo, hi));
        }
    }

    float af[16];
    #pragma unroll
    for (int p = 0; p < 8; p++) unpack2(acc[p], af[2 * p], af[2 * p + 1]);
    #pragma unroll
    for (int q = 0; q < 4; q++) {
        float4 o;
        o.x = af[q * 4 + 0]; o.y = af[q * 4 + 1];
        o.z = af[q * 4 + 2]; o.w = af[q * 4 + 3];
        *(float4*)(st + i_l * ST_STRIDE + dbase + q * 4) = o;
    }
    __syncthreads();

    if (tid < 128) {
        float S = 0.f, SS = 0.f;
        #pragma unroll 8
        for (int i = 0; i < 64; i++) {
            float v = st[i * ST_STRIDE + tid];
            S += v; SS += v * v;
        }
        g_ps[cta * 128 + tid]  = S;
        g_pss[cta * 128 + tid] = SS;
    }
    const int nb = node0 + i0;
    #pragma unroll
    for (int t = 0; t < 16; t++) {
        int idx = tid + t * 512;
        int i = idx >> 7;
        int d = idx & 127;
        g_P2[((nb + i) << 7) + d] = st[i * ST_STRIDE + d];
    }

    // last-block: reduce partials -> g_bstats (deterministic fixed order)
    __shared__ unsigned s_tk;
    __threadfence();
    if (tid == 0) s_tk = atomicAdd(&g_cnt, 1u);
    __syncthreads();
    if (s_tk == 127u) {
        __threadfence();
        const int d   = tid & 127;
        const int grp = tid >> 7;
        const float* ps  = g_ps  + grp * 32 * 128 + d;
        const float* pss = g_pss + grp * 32 * 128 + d;
        float S = 0.f, SS = 0.f;
        #pragma unroll 8
        for (int c = 0; c < 32; c++) {
            S  += ps[c * 128];
            SS += pss[c * 128];
        }
        st[grp * 128 + d]       = S;
        st[512 + grp * 128 + d] = SS;
        __syncthreads();
        if (tid < 128) {
            float St  = st[tid] + st[128 + tid] + st[256 + tid] + st[384 + tid];
            float SSt = st[512 + tid] + st[640 + tid] + st[768 + tid] + st[896 + tid];
            float mu  = St * (1.f / (float)NNODES);
            float var = SSt * (1.f / (float)NNODES) - mu * mu;
            float inv = 1.f / sqrtf(var + EPSV);
            float scale = inv * bn_g[tid];
            g_bstats[tid]       = scale;
            g_bstats[128 + tid] = bn_b[tid] - mu * scale;
        }
        __threadfence();
        if (tid == 0) g_cnt = 0u;
    }
}

// ============================================================================
// K1: branch 1 + fused output (unchanged from R14).
// ============================================================================
__global__ void __launch_bounds__(1024, 1)
k1_branch1(const float* __restrict__ X, const float* __restrict__ XYZ,
           const float* __restrict__ b1, const float* __restrict__ ln_g,
           const float* __restrict__ ln_b, float* __restrict__ out) {
    extern __shared__ float sm1[];
    float* ys   = sm1;                  // [128][128]          (16384 f)
    ull*   ysu  = (ull*)ys;
    ull*   wsd  = (ull*)(sm1 + 16384);  // [128 j][64 i] (w,w) (16384 f)
    float* xyzs = sm1 + 32768;          // [128][4]            (512 f)

    const int tid  = threadIdx.x;
    const int w    = tid >> 5;
    const int lane = tid & 31;
    const int iA   = w << 1;
    const int iB   = iA + 1;
    const int dbase = lane << 2;

    const int cta   = blockIdx.x;
    const int node0 = (cta >> 1) << 7;
    const int i0    = (cta & 1) << 6;

    {
        const float4* Yv = (const float4*)(g_Y + node0 * DIM);
        float4* ysv = (float4*)ys;
        #pragma unroll
        for (int t = 0; t < 4; t++) ysv[tid + t * 1024] = Yv[tid + t * 1024];
    }
    if (tid < 128) {
        const float* p = XYZ + (node0 + tid) * 3;
        xyzs[tid * 4 + 0] = p[0];
        xyzs[tid * 4 + 1] = p[1];
        xyzs[tid * 4 + 2] = p[2];
        xyzs[tid * 4 + 3] = 0.f;
    }
    __syncthreads();

    // wsd[j*64 + i] = (w_ij, w_ij); diag -> (1,1) (finite; corrected in epilogue)
    #pragma unroll
    for (int t = 0; t < 8; t++) {
        int idx = tid + t * 1024;
        int ii = idx & 63;
        int jj = idx >> 6;
        float dx = xyzs[((i0 + ii) << 2) + 0] - xyzs[(jj << 2) + 0];
        float dy = xyzs[((i0 + ii) << 2) + 1] - xyzs[(jj << 2) + 1];
        float dz = xyzs[((i0 + ii) << 2) + 2] - xyzs[(jj << 2) + 2];
        float d2 = dx * dx + dy * dy + dz * dz;
        float dist = d2 * rsqrt_ap(fmaxf(d2, 1e-30f));
        float wv = ex2_ap(-dist * LOG2E);
        wsd[(jj << 6) + ii] = pack2(wv, wv);
    }

    ull yiA[2], yiB[2], b1p[2];
    {
        const ull* b1u = (const ull*)b1;
        b1p[0] = b1u[lane * 2 + 0];
        b1p[1] = b1u[lane * 2 + 1];
    }
    __syncthreads();
    {
        int offA = (i0 + iA) * 64 + lane * 2;
        int offB = (i0 + iB) * 64 + lane * 2;
        yiA[0] = ysu[offA]; yiA[1] = ysu[offA + 1];
        yiB[0] = ysu[offB]; yiB[1] = ysu[offB + 1];
    }
    ull accA[2] = {0ULL, 0ULL}, accB[2] = {0ULL, 0ULL};

    #pragma unroll 4
    for (int j = 0; j < 128; j++) {
        ulonglong2 wv2 = *(const ulonglong2*)(wsd + (j << 6) + iA);
        ulonglong2 yj  = *(const ulonglong2*)(ysu + (j << 6) + lane * 2);
        ull yjp[2] = {yj.x, yj.y};
        #pragma unroll
        for (int p = 0; p < 2; p++) {
            float lo, hi;
            ull df = fma2(yjp[p], NEG1_2, yiA[p]);
            ull t  = fma2(wv2.x, df, b1p[p]);
            unpack2(t, lo, hi);
            lo = fmaxf(lo, 0.f); hi = fmaxf(hi, 0.f);
            accA[p] = add2(accA[p], pack2(lo, hi));

            df = fma2(yjp[p], NEG1_2, yiB[p]);
            t  = fma2(wv2.y, df, b1p[p]);
            unpack2(t, lo, hi);
            lo = fmaxf(lo, 0.f); hi = fmaxf(hi, 0.f);
            accB[p] = add2(accB[p], pack2(lo, hi));
        }
    }

    float afA[4], afB[4];
    #pragma unroll
    for (int p = 0; p < 2; p++) {
        float bl, bh; unpack2(b1p[p], bl, bh);
        float rb0 = fmaxf(bl, 0.f), rb1 = fmaxf(bh, 0.f);
        float lo, hi;
        unpack2(accA[p], lo, hi);
        afA[2 * p + 0] = lo - rb0;
        afA[2 * p + 1] = hi - rb1;
        unpack2(accB[p], lo, hi);
        afB[2 * p + 0] = lo - rb0;
        afB[2 * p + 1] = hi - rb1;
    }
    float sA = 0.f, qA = 0.f, sB = 0.f, qB = 0.f;
    #pragma unroll
    for (int k = 0; k < 4; k++) {
        sA += afA[k]; qA += afA[k] * afA[k];
        sB += afB[k]; qB += afB[k] * afB[k];
    }
    #pragma unroll
    for (int off = 16; off > 0; off >>= 1) {
        sA += __shfl_xor_sync(0xffffffffu, sA, off);
        qA += __shfl_xor_sync(0xffffffffu, qA, off);
        sB += __shfl_xor_sync(0xffffffffu, sB, off);
        qB += __shfl_xor_sync(0xffffffffu, qB, off);
    }
    float muA  = sA * (1.f / 128.f);
    float invA = 1.f / sqrtf(qA * (1.f / 128.f) - muA * muA + EPSV);
    float muB  = sB * (1.f / 128.f);
    float invB = 1.f / sqrtf(qB * (1.f / 128.f) - muB * muB + EPSV);

    float4 gv = *(const float4*)(ln_g + dbase);
    float4 bv = *(const float4*)(ln_b + dbase);
    float4 sc = *(const float4*)(g_bstats + dbase);
    float4 sh = *(const float4*)(g_bstats + 128 + dbase);

    int gbA = ((node0 + i0 + iA) << 7) + dbase;
    int gbB = ((node0 + i0 + iB) << 7) + dbase;
    {
        float4 xv = *(const float4*)(X + gbA);
        float4 pv = *(const float4*)(g_P2 + gbA);
        float4 o;
        o.x = xv.x + (afA[0] - muA) * invA * gv.x + bv.x + pv.x * sc.x + sh.x;
        o.y = xv.y + (afA[1] - muA) * invA * gv.y + bv.y + pv.y * sc.y + sh.y;
        o.z = xv.z + (afA[2] - muA) * invA * gv.z + bv.z + pv.z * sc.z + sh.z;
        o.w = xv.w + (afA[3] - muA) * invA * gv.w + bv.w + pv.w * sc.w + sh.w;
        *(float4*)(out + gbA) = o;
    }
    {
        float4 xv = *(const float4*)(X + gbB);
        float4 pv = *(const float4*)(g_P2 + gbB);
        float4 o;
        o.x = xv.x + (afB[0] - muB) * invB * gv.x + bv.x + pv.x * sc.x + sh.x;
        o.y = xv.y + (afB[1] - muB) * invB * gv.y + bv.y + pv.y * sc.y + sh.y;
        o.z = xv.z + (afB[2] - muB) * invB * gv.z + bv.z + pv.z * sc.z + sh.z;
        o.w = xv.w + (afB[3] - muB) * invB * gv.w + bv.w + pv.w * sc.w + sh.w;
        *(float4*)(out + gbB) = o;
    }
}

// ============================================================================
extern "C" void kernel_launch(void* const* d_in, const int* in_sizes, int n_in,
                              void* d_out, int out_size) {
    const float* X    = (const float*)d_in[0];
    const float* XYZ  = (const float*)d_in[1];
    const float* Wxyz = (const float*)d_in[2];
    const float* bn_g = (const float*)d_in[3];
    const float* bn_b = (const float*)d_in[4];
    const float* W1   = (const float*)d_in[5];
    const float* b1   = (const float*)d_in[6];
    const float* ln_g = (const float*)d_in[7];
    const float* ln_b = (const float*)d_in[8];
    float* out = (float*)d_out;

    const int smem0 = (2 * 128 + 2 * 64) * LDB * 2;            // 104448 B (~102 KB)
    const int smem1 = (16384 + 16384 + 512) * 4;               // ~130 KB
    const int smem2 = (16384 + 8448 + 512 + 384) * 4;          // ~102.9 KB

    cudaFuncSetAttribute(k0_gemm,    cudaFuncAttributeMaxDynamicSharedMemorySize, smem0);
    cudaFuncSetAttribute(k1_branch1, cudaFuncAttributeMaxDynamicSharedMemorySize, smem1);
    cudaFuncSetAttribute(k2_branch2, cudaFuncAttributeMaxDynamicSharedMemorySize, smem2);

    // Fork-join: k0 (legacy stream) || k2 (forked stream); k1 joins.
    cudaStream_t s1;
    cudaStreamCreateWithFlags(&s1, cudaStreamNonBlocking);
    cudaEvent_t evA, evB;
    cudaEventCreateWithFlags(&evA, cudaEventDisableTiming);
    cudaEventCreateWithFlags(&evB, cudaEventDisableTiming);

    cudaEventRecord(evA, 0);
    cudaStreamWaitEvent(s1, evA, 0);

    k0_gemm   <<<128, 256, smem0>>>(X, W1);                     // legacy stream
    k2_branch2<<<128, 512, smem2, s1>>>(XYZ, Wxyz, bn_g, bn_b); // forked stream

    cudaEventRecord(evB, s1);
    cudaStreamWaitEvent(0, evB, 0);

    k1_branch1<<<128, 1024, smem1>>>(X, XYZ, b1, ln_g, ln_b, out);
}

// round 16
// speedup vs baseline: 1.3432x; 1.0813x over previous
#include <cuda_runtime.h>
#include <cuda_bf16.h>
#include <mma.h>
#include <math.h>

using namespace nvcuda;

#define CLOUDS 64
#define PPC    128
#define DIM    128
#define NNODES (CLOUDS * PPC)
#define EPSV   1e-5f

typedef unsigned long long ull;

// ---------------- scratch ------------------------------------------------------
__device__ float g_Y[NNODES * DIM];     // X @ W1
__device__ float g_ps[128 * 128];
__device__ float g_pss[128 * 128];
__device__ float g_bstats[256];         // [0:128) scale, [128:256) shift
__device__ unsigned g_cnt;              // arrival ticket
__device__ unsigned g_cnt2;             // exit ticket (reset)
__device__ unsigned g_flag;             // bstats-ready flag

// ---------------- helpers ------------------------------------------------------
__device__ __forceinline__ ull pack2(float lo, float hi) {
    ull r; asm("mov.b64 %0, {%1, %2};" : "=l"(r) : "f"(lo), "f"(hi)); return r;
}
__device__ __forceinline__ void unpack2(ull v, float& lo, float& hi) {
    asm("mov.b64 {%0, %1}, %2;" : "=f"(lo), "=f"(hi) : "l"(v));
}
__device__ __forceinline__ ull fma2(ull a, ull b, ull c) {
    ull d; asm("fma.rn.f32x2 %0, %1, %2, %3;" : "=l"(d) : "l"(a), "l"(b), "l"(c)); return d;
}
__device__ __forceinline__ ull add2(ull a, ull b) {
    ull d; asm("add.rn.f32x2 %0, %1, %2;" : "=l"(d) : "l"(a), "l"(b)); return d;
}
__device__ __forceinline__ float rsqrt_ap(float x) {
    float r; asm("rsqrt.approx.f32 %0, %1;" : "=f"(r) : "f"(x)); return r;
}
__device__ __forceinline__ float ex2_ap(float x) {
    float r; asm("ex2.approx.f32 %0, %1;" : "=f"(r) : "f"(x)); return r;
}

#define NEG1_2 0xBF800000BF800000ULL
#define LOG2E  1.4426950408889634f

// ============================================================================
// K0: Y = X @ W1 on tensor cores (split-bf16, 3 terms) — unchanged from R15.
// ============================================================================
#define LDB 136

__global__ void __launch_bounds__(256, 1)
k0_gemm(const float* __restrict__ X, const float* __restrict__ W1) {
    extern __shared__ __nv_bfloat16 smb[];
    __nv_bfloat16* Whi = smb;                       // [128][136]
    __nv_bfloat16* Wlo = smb + 128 * LDB;           // [128][136]
    __nv_bfloat16* Xhi = smb + 2 * 128 * LDB;       // [64][136]
    __nv_bfloat16* Xlo = Xhi + 64 * LDB;            // [64][136]

    const int tid = threadIdx.x;
    const int r0  = blockIdx.x * 64;

    #pragma unroll
    for (int t = 0; t < 64; t++) {
        int idx = tid + t * 256;
        int r = idx >> 7, c = idx & 127;
        float v = W1[idx];
        __nv_bfloat16 h = __float2bfloat16(v);
        Whi[r * LDB + c] = h;
        Wlo[r * LDB + c] = __float2bfloat16(v - __bfloat162float(h));
    }
    #pragma unroll
    for (int t = 0; t < 32; t++) {
        int idx = tid + t * 256;
        int r = idx >> 7, c = idx & 127;
        float v = X[(r0 + r) * DIM + c];
        __nv_bfloat16 h = __float2bfloat16(v);
        Xhi[r * LDB + c] = h;
        Xlo[r * LDB + c] = __float2bfloat16(v - __bfloat162float(h));
    }
    __syncthreads();

    const int wid = tid >> 5;
    const int rw  = wid >> 1;
    const int cw  = wid & 1;

    wmma::fragment<wmma::accumulator, 16, 16, 16, float> acc[4];
    #pragma unroll
    for (int c = 0; c < 4; c++) wmma::fill_fragment(acc[c], 0.f);

    #pragma unroll
    for (int ks = 0; ks < 8; ks++) {
        wmma::fragment<wmma::matrix_a, 16, 16, 16, __nv_bfloat16, wmma::row_major> ahi, alo;
        wmma::load_matrix_sync(ahi, Xhi + rw * 16 * LDB + ks * 16, LDB);
        wmma::load_matrix_sync(alo, Xlo + rw * 16 * LDB + ks * 16, LDB);
        #pragma unroll
        for (int c = 0; c < 4; c++) {
            wmma::fragment<wmma::matrix_b, 16, 16, 16, __nv_bfloat16, wmma::row_major> bhi, blo;
            int col = cw * 64 + c * 16;
            wmma::load_matrix_sync(bhi, Whi + ks * 16 * LDB + col, LDB);
            wmma::load_matrix_sync(blo, Wlo + ks * 16 * LDB + col, LDB);
            wmma::mma_sync(acc[c], ahi, bhi, acc[c]);
            wmma::mma_sync(acc[c], ahi, blo, acc[c]);
            wmma::mma_sync(acc[c], alo, bhi, acc[c]);
        }
    }

    #pragma unroll
    for (int c = 0; c < 4; c++) {
        wmma::store_matrix_sync(g_Y + (ull)(r0 + rw * 16) * DIM + cw * 64 + c * 16,
                                acc[c], DIM, wmma::mem_row_major);
    }
}

// ============================================================================
// KFUSED: branches 1+2 merged (mega loop, without the in-kernel GEMM).
// 128 CTAs x 1024 threads; warp = i-pair, lane = 4-d chunk.
// One j-loop accumulates p1 (w*(yi-yj)+b1 relu) and p2 (zi-zj relu).
// BN stats via resident-grid ticket + spin (proven in R12 mega).
//   out = x + LN(p1)*ln_g + ln_b + p2*bn_scale + bn_shift
// smem 195.5 KB.
// ============================================================================
#define SMF_FLOATS 50048

__global__ void __launch_bounds__(1024, 1)
kfused(const float* __restrict__ X, const float* __restrict__ XYZ,
       const float* __restrict__ Wxyz, const float* __restrict__ bn_g,
       const float* __restrict__ bn_b, const float* __restrict__ b1,
       const float* __restrict__ ln_g, const float* __restrict__ ln_b,
       float* __restrict__ out) {
    extern __shared__ float sm[];
    float* ys   = sm;                    // [128][128]           (64 KB)
    ull*   ysu  = (ull*)ys;
    ull*   wsd  = (ull*)(sm + 16384);    // [128 j][64 i] (w,w)  (64 KB) -> BN stage
    float* zs   = sm + 32768;            // [128][128]           (64 KB) -> reduce stage
    ull*   zsu  = (ull*)zs;
    float* xyzs = sm + 49152;            // [128][4]
    float* wxs  = sm + 49664;            // [3][128]

    const int tid  = threadIdx.x;
    const int w    = tid >> 5;
    const int lane = tid & 31;
    const int iA   = w << 1;
    const int iB   = iA + 1;
    const int dbase = lane << 2;

    const int cta   = blockIdx.x;
    const int node0 = (cta >> 1) << 7;
    const int i0    = (cta & 1) << 6;

    // ---- stage Y, xyz, Wxyz ----
    {
        const float4* Yv = (const float4*)(g_Y + node0 * DIM);
        float4* ysv = (float4*)ys;
        #pragma unroll
        for (int t = 0; t < 4; t++) ysv[tid + t * 1024] = Yv[tid + t * 1024];
    }
    if (tid < 128) {
        const float* p = XYZ + (node0 + tid) * 3;
        xyzs[tid * 4 + 0] = p[0];
        xyzs[tid * 4 + 1] = p[1];
        xyzs[tid * 4 + 2] = p[2];
        xyzs[tid * 4 + 3] = 0.f;
    } else if (tid >= 512 && tid < 896) {
        wxs[tid - 512] = Wxyz[tid - 512];
    }
    __syncthreads();

    // ---- zs (full cloud) and wsd (this CTA's 64 i) ----
    #pragma unroll
    for (int t = 0; t < 16; t++) {
        int idx = tid + t * 1024;
        int jn = idx >> 7;
        int d  = idx & 127;
        zs[idx] = xyzs[(jn << 2) + 0] * wxs[d]
                + xyzs[(jn << 2) + 1] * wxs[128 + d]
                + xyzs[(jn << 2) + 2] * wxs[256 + d];
    }
    #pragma unroll
    for (int t = 0; t < 8; t++) {
        int idx = tid + t * 1024;
        int ii = idx & 63;
        int jj = idx >> 6;
        float dx = xyzs[((i0 + ii) << 2) + 0] - xyzs[(jj << 2) + 0];
        float dy = xyzs[((i0 + ii) << 2) + 1] - xyzs[(jj << 2) + 1];
        float dz = xyzs[((i0 + ii) << 2) + 2] - xyzs[(jj << 2) + 2];
        float d2 = dx * dx + dy * dy + dz * dz;
        float dist = d2 * rsqrt_ap(fmaxf(d2, 1e-30f));
        float wv = ex2_ap(-dist * LOG2E);
        wsd[(jj << 6) + ii] = pack2(wv, wv);   // diag -> (1,1); corrected below
    }

    ull b1p[2];
    {
        const ull* b1u = (const ull*)b1;
        b1p[0] = b1u[lane * 2 + 0];
        b1p[1] = b1u[lane * 2 + 1];
    }
    __syncthreads();

    ull yiA[2], yiB[2], ziA[2], ziB[2];
    {
        int offA = (i0 + iA) * 64 + lane * 2;
        int offB = (i0 + iB) * 64 + lane * 2;
        yiA[0] = ysu[offA]; yiA[1] = ysu[offA + 1];
        yiB[0] = ysu[offB]; yiB[1] = ysu[offB + 1];
        ziA[0] = zsu[offA]; ziA[1] = zsu[offA + 1];
        ziB[0] = zsu[offB]; ziB[1] = zsu[offB + 1];
    }
    ull a1A[2] = {0ULL, 0ULL}, a1B[2] = {0ULL, 0ULL};
    ull a2A[2] = {0ULL, 0ULL}, a2B[2] = {0ULL, 0ULL};

    // ---- fused main loop over j ----
    #pragma unroll 4
    for (int j = 0; j < 128; j++) {
        ulonglong2 wv2 = *(const ulonglong2*)(wsd + (j << 6) + iA);
        ulonglong2 yj  = *(const ulonglong2*)(ysu + (j << 6) + lane * 2);
        ulonglong2 zj  = *(const ulonglong2*)(zsu + (j << 6) + lane * 2);
        ull yjp[2] = {yj.x, yj.y};
        ull zjp[2] = {zj.x, zj.y};
        #pragma unroll
        for (int p = 0; p < 2; p++) {
            float lo, hi;
            ull df = fma2(yjp[p], NEG1_2, yiA[p]);
            ull t  = fma2(wv2.x, df, b1p[p]);
            unpack2(t, lo, hi);
            lo = fmaxf(lo, 0.f); hi = fmaxf(hi, 0.f);
            a1A[p] = add2(a1A[p], pack2(lo, hi));

            df = fma2(yjp[p], NEG1_2, yiB[p]);
            t  = fma2(wv2.y, df, b1p[p]);
            unpack2(t, lo, hi);
            lo = fmaxf(lo, 0.f); hi = fmaxf(hi, 0.f);
            a1B[p] = add2(a1B[p], pack2(lo, hi));

            ull dz = fma2(zjp[p], NEG1_2, ziA[p]);
            unpack2(dz, lo, hi);
            lo = fmaxf(lo, 0.f); hi = fmaxf(hi, 0.f);
            a2A[p] = add2(a2A[p], pack2(lo, hi));

            dz = fma2(zjp[p], NEG1_2, ziB[p]);
            unpack2(dz, lo, hi);
            lo = fmaxf(lo, 0.f); hi = fmaxf(hi, 0.f);
            a2B[p] = add2(a2B[p], pack2(lo, hi));
        }
    }

    // ---- LN (warp shuffles) + unpack p2 ----
    float afA[4], afB[4], pA[4], pB[4];
    #pragma unroll
    for (int p = 0; p < 2; p++) {
        float bl, bh; unpack2(b1p[p], bl, bh);
        float rb0 = fmaxf(bl, 0.f), rb1 = fmaxf(bh, 0.f);
        float lo, hi;
        unpack2(a1A[p], lo, hi);
        afA[2 * p + 0] = lo - rb0;  afA[2 * p + 1] = hi - rb1;
        unpack2(a1B[p], lo, hi);
        afB[2 * p + 0] = lo - rb0;  afB[2 * p + 1] = hi - rb1;
        unpack2(a2A[p], lo, hi);
        pA[2 * p + 0] = lo;  pA[2 * p + 1] = hi;
        unpack2(a2B[p], lo, hi);
        pB[2 * p + 0] = lo;  pB[2 * p + 1] = hi;
    }
    float sA = 0.f, qA = 0.f, sB = 0.f, qB = 0.f;
    #pragma unroll
    for (int k = 0; k < 4; k++) {
        sA += afA[k]; qA += afA[k] * afA[k];
        sB += afB[k]; qB += afB[k] * afB[k];
    }
    #pragma unroll
    for (int off = 16; off > 0; off >>= 1) {
        sA += __shfl_xor_sync(0xffffffffu, sA, off);
        qA += __shfl_xor_sync(0xffffffffu, qA, off);
        sB += __shfl_xor_sync(0xffffffffu, sB, off);
        qB += __shfl_xor_sync(0xffffffffu, qB, off);
    }
    float muA  = sA * (1.f / 128.f);
    float invA = 1.f / sqrtf(qA * (1.f / 128.f) - muA * muA + EPSV);
    float muB  = sB * (1.f / 128.f);
    float invB = 1.f / sqrtf(qB * (1.f / 128.f) - muB * muB + EPSV);

    // ---- BN partials -> global (stage in wsd area, free after loop) ----
    float* stg = (float*)wsd;
    __syncthreads();
    {
        float4 s4, q4;
        s4.x = pA[0] + pB[0]; s4.y = pA[1] + pB[1];
        s4.z = pA[2] + pB[2]; s4.w = pA[3] + pB[3];
        q4.x = pA[0] * pA[0] + pB[0] * pB[0];
        q4.y = pA[1] * pA[1] + pB[1] * pB[1];
        q4.z = pA[2] * pA[2] + pB[2] * pB[2];
        q4.w = pA[3] * pA[3] + pB[3] * pB[3];
        *(float4*)(stg + w * 128 + dbase)        = s4;
        *(float4*)(stg + 4096 + w * 128 + dbase) = q4;
    }
    __syncthreads();
    if (tid < 128) {
        float S = 0.f, SS = 0.f;
        #pragma unroll 8
        for (int ww = 0; ww < 32; ww++) {
            S  += stg[ww * 128 + tid];
            SS += stg[4096 + ww * 128 + tid];
        }
        g_ps[cta * 128 + tid]  = S;
        g_pss[cta * 128 + tid] = SS;
    }

    // ---- resident-grid sync: last CTA computes bstats ----
    __shared__ unsigned s_tk;
    __threadfence();
    if (tid == 0) s_tk = atomicAdd(&g_cnt, 1u);
    __syncthreads();
    if (s_tk == 127u) {
        __threadfence();
        const int d   = tid & 127;
        const int grp = tid >> 7;   // 0..7, 16 CTAs each
        const float* ps  = g_ps  + grp * 16 * 128 + d;
        const float* pss = g_pss + grp * 16 * 128 + d;
        float S = 0.f, SS = 0.f;
        #pragma unroll 8
        for (int c = 0; c < 16; c++) {
            S  += ps[c * 128];
            SS += pss[c * 128];
        }
        zs[grp * 128 + d]        = S;
        zs[1024 + grp * 128 + d] = SS;
        __syncthreads();
        if (tid < 128) {
            float St = 0.f, SSt = 0.f;
            #pragma unroll
            for (int g = 0; g < 8; g++) {
                St  += zs[g * 128 + tid];
                SSt += zs[1024 + g * 128 + tid];
            }
            float mu  = St * (1.f / (float)NNODES);
            float var = SSt * (1.f / (float)NNODES) - mu * mu;
            float inv = 1.f / sqrtf(var + EPSV);
            float scale = inv * bn_g[tid];
            g_bstats[tid]       = scale;
            g_bstats[128 + tid] = bn_b[tid] - mu * scale;
        }
        __syncthreads();
        if (tid == 0) {
            __threadfence();
            atomicExch(&g_flag, 1u);
        }
    } else if (tid == 0) {
        while (atomicAdd(&g_flag, 0u) == 0u) __nanosleep(64);
    }
    __syncthreads();
    __threadfence();

    // ---- final write: out = x + LN(p1) + BN(p2) ----
    float4 gv = *(const float4*)(ln_g + dbase);
    float4 bv = *(const float4*)(ln_b + dbase);
    float4 sc = *(const float4*)(g_bstats + dbase);
    float4 sh = *(const float4*)(g_bstats + 128 + dbase);

    int gbA = ((node0 + i0 + iA) << 7) + dbase;
    int gbB = ((node0 + i0 + iB) << 7) + dbase;
    {
        float4 xv = *(const float4*)(X + gbA);
        float4 o;
        o.x = xv.x + (afA[0] - muA) * invA * gv.x + bv.x + pA[0] * sc.x + sh.x;
        o.y = xv.y + (afA[1] - muA) * invA * gv.y + bv.y + pA[1] * sc.y + sh.y;
        o.z = xv.z + (afA[2] - muA) * invA * gv.z + bv.z + pA[2] * sc.z + sh.z;
        o.w = xv.w + (afA[3] - muA) * invA * gv.w + bv.w + pA[3] * sc.w + sh.w;
        *(float4*)(out + gbA) = o;
    }
    {
        float4 xv = *(const float4*)(X + gbB);
        float4 o;
        o.x = xv.x + (afB[0] - muB) * invB * gv.x + bv.x + pB[0] * sc.x + sh.x;
        o.y = xv.y + (afB[1] - muB) * invB * gv.y + bv.y + pB[1] * sc.y + sh.y;
        o.z = xv.z + (afB[2] - muB) * invB * gv.z + bv.z + pB[2] * sc.z + sh.z;
        o.w = xv.w + (afB[3] - muB) * invB * gv.w + bv.w + pB[3] * sc.w + sh.w;
        *(float4*)(out + gbB) = o;
    }

    // ---- reset for next (graph-replayed) launch ----
    if (tid == 0) {
        unsigned t2 = atomicAdd(&g_cnt2, 1u);
        if (t2 == 127u) {
            g_cnt  = 0u;
            g_cnt2 = 0u;
            g_flag = 0u;
        }
    }
}

// ============================================================================
extern "C" void kernel_launch(void* const* d_in, const int* in_sizes, int n_in,
                              void* d_out, int out_size) {
    const float* X    = (const float*)d_in[0];
    const float* XYZ  = (const float*)d_in[1];
    const float* Wxyz = (const float*)d_in[2];
    const float* bn_g = (const float*)d_in[3];
    const float* bn_b = (const float*)d_in[4];
    const float* W1   = (const float*)d_in[5];
    const float* b1   = (const float*)d_in[6];
    const float* ln_g = (const float*)d_in[7];
    const float* ln_b = (const float*)d_in[8];
    float* out = (float*)d_out;

    const int smem0 = (2 * 128 + 2 * 64) * LDB * 2;   // ~102 KB
    const int smemF = SMF_FLOATS * 4;                 // ~195.5 KB

    cudaFuncSetAttribute(k0_gemm, cudaFuncAttributeMaxDynamicSharedMemorySize, smem0);
    cudaFuncSetAttribute(kfused,  cudaFuncAttributeMaxDynamicSharedMemorySize, smemF);

    k0_gemm<<<128, 256, smem0>>>(X, W1);
    kfused <<<128, 1024, smemF>>>(X, XYZ, Wxyz, bn_g, bn_b, b1, ln_g, ln_b, out);
}